// round 6
// baseline (speedup 1.0000x reference)
#include <cuda_runtime.h>

#define B_  16
#define C_  8
#define H_  512
#define W_  512
#define TW  32           // tile width
#define TH  16           // tile height
#define HW_ 34           // TW + 2
#define HH_ 18           // TH + 2
#define SROW 35          // padded smem row (float2 elems)
#define NTHREADS 256
#define NBLOCKS ((W_/TW)*(H_/TH)*B_)                          /* 8192 */
#define SMEM_BYTES (C_ * HH_ * SROW * (int)sizeof(float2))    /* 40320 */

__device__ double   g_acc;    // zero-initialized at module load
__device__ unsigned g_tick;   // zero-initialized at module load

__global__ __launch_bounds__(NTHREADS, 4)
void k_main(const float* __restrict__ cmap,
            const float* __restrict__ target,
            const float* __restrict__ con,
            float* __restrict__ out) {
    extern __shared__ float2 s[];   // [C_][HH_][SROW] : (p, log p)

    const int w0 = blockIdx.x * TW;
    const int h0 = blockIdx.y * TH;
    const int b  = blockIdx.z;
    const int tid = threadIdx.x;

    // ---- load phase: sigmoid + log-sigmoid computed ONCE per element ------
    const float* cb = cmap + (size_t)b * C_ * H_ * W_;
    for (int i = tid; i < C_ * HH_ * HW_; i += NTHREADS) {
        int c   = i / (HH_ * HW_);
        int rem = i - c * (HH_ * HW_);
        int hy  = rem / HW_;
        int wx  = rem - hy * HW_;
        int gh = h0 - 1 + hy;
        int gw = w0 - 1 + wx;
        float p, lp;
        if ((unsigned)gh < H_ && (unsigned)gw < W_) {
            float x  = cb[((size_t)c * H_ + gh) * W_ + gw];
            float e  = __expf(-fabsf(x));            // EX2
            float op = 1.0f + e;
            float l  = __logf(op);                   // LG2 (= log1p(e), e<=1)
            float r  = __fdividef(1.0f, op);         // RCP
            p  = (x >= 0.0f) ? r : e * r;            // sigmoid(x)
            lp = fminf(x, 0.0f) - l;                 // log sigmoid(x)
        } else {
            p = 0.0f; lp = -1e9f;                    // zero pad outside image
        }
        s[(c * HH_ + hy) * SROW + wx] = make_float2(p, lp);
    }
    __syncthreads();

    // ---- compute phase: 2 consecutive pixels per thread, float2 LDG -------
    const int row = tid >> 4;          // 0..15
    const int pxb = (tid & 15) * 2;    // 0,2,...,30
    const int gh  = h0 + row;
    const int gw  = w0 + pxb;

    const float2* con2  = (const float2*)con;
    const float2* cmap2 = (const float2*)cmap;
    const float2* tgt2  = (const float2*)target;
    const size_t base = ((((size_t)b * C_) * H_ + gh) * W_ + gw) >> 1; // ch0, fl2
    const size_t chs  = (size_t)(H_ * W_) >> 1;                         // ch stride

    float acc = 0.0f;
    float2 tcv[8];
    float st0 = 0.0f, st1 = 0.0f;
    #pragma unroll
    for (int c = 0; c < 8; c++) {
        tcv[c] = con2[base + c * chs];             // con_target (cold)
        st0 += tcv[c].x;  st1 += tcv[c].y;
    }

    // conmap BCE (weight 0.8): log(1-p) = log p - x (exact identity)
    #pragma unroll
    for (int c = 0; c < 8; c++) {
        float2 xv = cmap2[base + c * chs];         // L1/L2 hit (just loaded)
        float2 s0 = s[(c * HH_ + row + 1) * SROW + pxb + 1];
        float2 s1 = s[(c * HH_ + row + 1) * SROW + pxb + 2];
        float lp0 = fmaxf(s0.y, -100.0f), lm0 = fmaxf(s0.y - xv.x, -100.0f);
        float lp1 = fmaxf(s1.y, -100.0f), lm1 = fmaxf(s1.y - xv.y, -100.0f);
        acc += 0.8f * ((tcv[c].x != 0.0f) ? lp0 : lm0);
        acc += 0.8f * ((tcv[c].y != 0.0f) ? lp1 : lm1);
    }

    // votes / bimap BCE (weight 0.2). vote k: center ch k x ch 7-k at nbr k
    const int DH[8] = {-1, -1, -1,  0, 0,  1, 1, 1};
    const int DW[8] = {-1,  0,  1, -1, 1, -1, 0, 1};
    float vmin0 = 1e30f, vmin1 = 1e30f, vs0 = 0.0f, vs1 = 0.0f;
    #pragma unroll
    for (int k = 0; k < 8; k++) {
        float2 c0 = s[(k * HH_ + row + 1) * SROW + pxb + 1];
        float2 c1 = s[(k * HH_ + row + 1) * SROW + pxb + 2];
        const int nrow = row + 1 + DH[k];
        float2 n0 = s[((7 - k) * HH_ + nrow) * SROW + pxb + 1 + DW[k]];
        float2 n1 = s[((7 - k) * HH_ + nrow) * SROW + pxb + 2 + DW[k]];
        float v0 = c0.x * n0.x,  v1 = c1.x * n1.x;
        float lv0 = fmaxf(c0.y + n0.y, -100.0f);          // log(pa*pb), free
        float lv1 = fmaxf(c1.y + n1.y, -100.0f);
        float l10 = fmaxf(__logf(fmaf(-c0.x, n0.x, 1.0f)), -100.0f);
        float l11 = fmaxf(__logf(fmaf(-c1.x, n1.x, 1.0f)), -100.0f);
        acc += 0.2f * ((tcv[k].x != 0.0f) ? lv0 : l10);
        acc += 0.2f * ((tcv[k].y != 0.0f) ? lv1 : l11);
        vmin0 = fminf(vmin0, v0);  vmin1 = fminf(vmin1, v1);
        vs0 += v0;  vs1 += v1;
    }

    // decouple / de loss (weight 1.0)
    {
        float2 tt = tgt2[(((size_t)b * H_ + gh) * W_ + gw) >> 1];
        bool  e0  = (st0 > 0.0f) && (st0 < 8.0f);
        bool  e1  = (st1 > 0.0f) && (st1 < 8.0f);
        float g0 = vs0 * 0.125f, g1 = vs1 * 0.125f;
        float da0 = e0 ? (1.0f - vmin0) : g0;
        float db0 = e0 ? vmin0 : (1.0f - g0);
        float da1 = e1 ? (1.0f - vmin1) : g1;
        float db1 = e1 ? vmin1 : (1.0f - g1);
        float ld0 = fmaxf(__logf(da0), -100.0f), lm0 = fmaxf(__logf(db0), -100.0f);
        float ld1 = fmaxf(__logf(da1), -100.0f), lm1 = fmaxf(__logf(db1), -100.0f);
        acc += (tt.x != 0.0f) ? ld0 : lm0;
        acc += (tt.y != 0.0f) ? ld1 : lm1;
    }

    // ---- block reduction + global accumulate -------------------------------
    #pragma unroll
    for (int off = 16; off; off >>= 1)
        acc += __shfl_xor_sync(0xFFFFFFFFu, acc, off);

    __shared__ float warpsum[8];
    if ((tid & 31) == 0) warpsum[tid >> 5] = acc;
    __syncthreads();
    if (tid < 8) {
        float v = warpsum[tid];
        #pragma unroll
        for (int off = 4; off; off >>= 1)
            v += __shfl_xor_sync(0xFFu, v, off);
        if (tid == 0) atomicAdd(&g_acc, (double)v);
    }

    // ---- last block finalizes: write out, reset accumulator for next replay
    if (tid == 0) {
        __threadfence();
        unsigned t = atomicAdd(&g_tick, 1u);
        if (t == (unsigned)(NBLOCKS - 1)) {
            __threadfence();
            double total = atomicAdd(&g_acc, 0.0);
            out[0] = (float)(-total);
            g_acc  = 0.0;
            g_tick = 0u;
            __threadfence();
        }
    }
}

extern "C" void kernel_launch(void* const* d_in, const int* in_sizes, int n_in,
                              void* d_out, int out_size) {
    const float* cmap   = (const float*)d_in[0];
    const float* target = (const float*)d_in[1];
    const float* con    = (const float*)d_in[2];

    dim3 grid(W_ / TW, H_ / TH, B_);
    k_main<<<grid, NTHREADS, SMEM_BYTES>>>(cmap, target, con, (float*)d_out);
}

// round 7
// speedup vs baseline: 1.4076x; 1.4076x over previous
#include <cuda_runtime.h>

#define B_  16
#define C_  8
#define H_  512
#define W_  512
#define TW  32           // tile width
#define TH  16           // tile height
#define HW_ 34           // TW + 2
#define HH_ 18           // TH + 2
#define SROW 35          // smem row stride (floats)
#define PLANE (C_ * HH_ * SROW)          /* 5670 floats */
#define NTHREADS 256
#define NBLOCKS ((W_/TW)*(H_/TH)*B_)     /* 8192 */

__device__ double   g_acc;    // zero-initialized at module load
__device__ unsigned g_tick;   // zero-initialized at module load

__device__ __forceinline__ void sigmoid_pair(float x, float& p, float& lp) {
    float e  = __expf(-fabsf(x));            // EX2
    float op = 1.0f + e;
    float l  = __logf(op);                   // LG2 (= log1p(e), e<=1)
    float r  = __fdividef(1.0f, op);         // RCP
    p  = (x >= 0.0f) ? r : e * r;            // sigmoid(x)
    lp = fminf(x, 0.0f) - l;                 // log sigmoid(x)
}

__global__ __launch_bounds__(NTHREADS)
void k_main(const float* __restrict__ cmap,
            const float* __restrict__ target,
            const float* __restrict__ con,
            float* __restrict__ out) {
    __shared__ float s_p[PLANE];
    __shared__ float s_lp[PLANE];

    const int w0  = blockIdx.x * TW;
    const int h0  = blockIdx.y * TH;
    const int b   = blockIdx.z;
    const int tid = threadIdx.x;
    const int lane = tid & 31;
    const int wrp  = tid >> 5;     // 0..7

    // ---- load phase: sigmoid + log-sigmoid ONCE per element, no div/mod ---
    const float* cb = cmap + (size_t)b * C_ * H_ * W_;

    // main pass: lane = halo column 0..31; warp w handles rows w, w+8, w+16
    {
        const int gw = w0 - 1 + lane;
        const bool win = (unsigned)gw < W_;
        #pragma unroll
        for (int c = 0; c < C_; c++) {
            #pragma unroll
            for (int hy = 0; hy < HH_; hy += 8) {
                int row = hy + wrp;
                if (row >= HH_) break;               // only wrp<2 at hy=16
                int gh = h0 - 1 + row;
                float p = 0.0f, lp = -1e9f;
                if (win && (unsigned)gh < H_) {
                    float x = cb[((size_t)c * H_ + gh) * W_ + gw];
                    sigmoid_pair(x, p, lp);
                }
                int si = (c * HH_ + row) * SROW + lane;
                s_p[si]  = p;
                s_lp[si] = lp;
            }
        }
    }
    // epilogue: halo columns 32,33 (2 per row-job, 8*18*2 = 288 elements)
    for (int idx = tid; idx < C_ * HH_ * 2; idx += NTHREADS) {
        int c   = idx / (HH_ * 2);
        int rem = idx - c * (HH_ * 2);
        int row = rem >> 1;
        int wx  = 32 + (rem & 1);
        int gh  = h0 - 1 + row;
        int gw  = w0 - 1 + wx;
        float p = 0.0f, lp = -1e9f;
        if (((unsigned)gh < H_) && ((unsigned)gw < W_)) {
            float x = cb[((size_t)c * H_ + gh) * W_ + gw];
            sigmoid_pair(x, p, lp);
        }
        int si = (c * HH_ + row) * SROW + wx;
        s_p[si]  = p;
        s_lp[si] = lp;
    }
    __syncthreads();

    // ---- compute phase: 1 px/lane, 2 rows/thread; conflict-free LDS.32 ----
    // vote k: center ch k  x  ch 7-k at neighbor offset (DH[k], DW[k])
    const int DH[8] = {-1, -1, -1,  0, 0,  1, 1, 1};
    const int DW[8] = {-1,  0,  1, -1, 1, -1, 0, 1};

    float acc = 0.0f;
    #pragma unroll
    for (int q = 0; q < 2; q++) {
        const int py = wrp + q * 8;          // tile row 0..15
        const int gh = h0 + py;
        const int gw = w0 + lane;
        const size_t pix  = ((size_t)b * C_ * H_ + (size_t)py * 0 + 0); // (unused)
        const size_t gbase = (((size_t)b * C_) * H_ + gh) * W_ + gw;     // ch 0
        const int    sbase = (py + 1) * SROW + lane + 1;

        float pc[8], lpc[8], tc[8];
        float sum_t = 0.0f;
        #pragma unroll
        for (int c = 0; c < 8; c++) {
            int si = c * (HH_ * SROW) + sbase;
            float lp = s_lp[si];
            pc[c]  = s_p[si];
            lpc[c] = lp;
            float t = con[gbase + (size_t)c * (H_ * W_)];   // cold read
            float x = cmap[gbase + (size_t)c * (H_ * W_)];  // L1 hit
            tc[c] = t;
            sum_t += t;
            // conmap BCE (w=0.8): log(1-p) = log p - x (exact identity)
            float a  = fmaxf(lp, -100.0f);
            float bb = fmaxf(lp - x, -100.0f);
            acc += 0.8f * ((t != 0.0f) ? a : bb);
        }

        // votes / bimap BCE (w=0.2)
        float vmin = 1e30f, vsum = 0.0f;
        #pragma unroll
        for (int k = 0; k < 8; k++) {
            int ni = (7 - k) * (HH_ * SROW) + (py + 1 + DH[k]) * SROW
                     + (lane + 1 + DW[k]);
            float np  = s_p[ni];
            float nlp = s_lp[ni];
            float v    = pc[k] * np;
            float lv   = fmaxf(lpc[k] + nlp, -100.0f);       // log(pa*pb), free
            float l1mv = fmaxf(__logf(fmaf(-pc[k], np, 1.0f)), -100.0f);
            acc += 0.2f * ((tc[k] != 0.0f) ? lv : l1mv);
            vmin = fminf(vmin, v);
            vsum += v;
        }

        // decouple / de loss (w=1.0)
        bool  edge = (sum_t > 0.0f) && (sum_t < 8.0f);
        float glo  = vsum * 0.125f;
        float da   = edge ? (1.0f - vmin) : glo;
        float db   = edge ? vmin : (1.0f - glo);
        float ld   = fmaxf(__logf(da), -100.0f);
        float lm   = fmaxf(__logf(db), -100.0f);
        float tt   = target[((size_t)b * H_ + gh) * W_ + gw];
        acc += (tt != 0.0f) ? ld : lm;
    }

    // ---- block reduction + global accumulate -------------------------------
    #pragma unroll
    for (int off = 16; off; off >>= 1)
        acc += __shfl_xor_sync(0xFFFFFFFFu, acc, off);

    __shared__ float warpsum[8];
    if (lane == 0) warpsum[wrp] = acc;
    __syncthreads();
    if (tid < 8) {
        float v = warpsum[tid];
        #pragma unroll
        for (int off = 4; off; off >>= 1)
            v += __shfl_xor_sync(0xFFu, v, off);
        if (tid == 0) atomicAdd(&g_acc, (double)v);
    }

    // ---- last block finalizes: write out, reset accumulator for next replay
    if (tid == 0) {
        __threadfence();
        unsigned t = atomicAdd(&g_tick, 1u);
        if (t == (unsigned)(NBLOCKS - 1)) {
            __threadfence();
            double total = atomicAdd(&g_acc, 0.0);
            out[0] = (float)(-total);
            g_acc  = 0.0;
            g_tick = 0u;
            __threadfence();
        }
    }
}

extern "C" void kernel_launch(void* const* d_in, const int* in_sizes, int n_in,
                              void* d_out, int out_size) {
    const float* cmap   = (const float*)d_in[0];
    const float* target = (const float*)d_in[1];
    const float* con    = (const float*)d_in[2];

    dim3 grid(W_ / TW, H_ / TH, B_);
    k_main<<<grid, NTHREADS>>>(cmap, target, con, (float*)d_out);
}

// round 9
// speedup vs baseline: 2.0484x; 1.4552x over previous
#include <cuda_runtime.h>

#define B_  16
#define C_  8
#define H_  512
#define W_  512
#define TW  32           // tile width
#define TH  16           // tile height
#define HW_ 34           // TW + 2
#define HH_ 18           // TH + 2
#define SROW 35          // smem row stride (floats)
#define PLANE (C_ * HH_ * SROW)          /* 5040 floats */
#define NTHREADS 256
#define NBLOCKS ((W_/TW)*(H_/TH)*B_)     /* 8192 */
#define CHS ((size_t)H_ * W_)            /* channel stride */

__device__ double   g_acc;    // zero-initialized at module load
__device__ unsigned g_tick;   // zero-initialized at module load

__device__ __forceinline__ void sigmoid_pair(float x, float& p, float& lp) {
    float e  = __expf(-fabsf(x));            // EX2
    float op = 1.0f + e;
    float l  = __logf(op);                   // LG2 (= log1p(e), e<=1)
    float r  = __fdividef(1.0f, op);         // RCP
    p  = (x >= 0.0f) ? r : e * r;            // sigmoid(x)
    lp = fminf(x, 0.0f) - l;                 // log sigmoid(x)
}

__global__ __launch_bounds__(NTHREADS)
void k_main(const float* __restrict__ cmap,
            const float* __restrict__ target,
            const float* __restrict__ con,
            float* __restrict__ out) {
    __shared__ float s_p[PLANE];
    __shared__ float s_lp[PLANE];
    __shared__ unsigned char s_mask[TH * TW];   // packed con bits per pixel

    const int w0  = blockIdx.x * TW;
    const int h0  = blockIdx.y * TH;
    const int b   = blockIdx.z;
    const int tid = threadIdx.x;
    const int lane = tid & 31;
    const int wrp  = tid >> 5;     // 0..7

    float acc = 0.0f;

    // ==== load phase: lane = halo col 1..32 (in-tile cols, always in-image).
    // Computes sigmoid/log-sigmoid once per element AND fuses the conmap BCE
    // (w=0.8) + con bitmask packing for in-tile elements while x/lp are live.
    {
        const int wx = lane + 1;           // halo column
        const int gw = w0 + lane;          // global col, 0..511 always valid
        #pragma unroll
        for (int j = 0; j < 3; j++) {
            int row = wrp + j * 8;
            if (row >= HH_) break;         // j==2 only for wrp<2
            int gh = h0 - 1 + row;
            bool inimg  = (unsigned)gh < H_;
            bool intile = (row >= 1) && (row <= TH);   // implies inimg
            long goff = ((long)(b * C_) * H_ + gh) * W_ + gw;
            unsigned mask = 0;
            #pragma unroll
            for (int c = 0; c < 8; c++) {
                float p = 0.0f, lp = -1e9f, x = 0.0f;
                if (inimg) {
                    x = cmap[goff + (long)c * (long)CHS];
                    sigmoid_pair(x, p, lp);
                }
                int si = (c * HH_ + row) * SROW + wx;
                s_p[si]  = p;
                s_lp[si] = lp;
                if (intile) {
                    float t = __ldcs(&con[goff + (long)c * (long)CHS]);
                    mask |= (t != 0.0f ? 1u : 0u) << c;
                    float a  = fmaxf(lp, -100.0f);
                    float bb = fmaxf(lp - x, -100.0f);   // log(1-p)=lp-x exact
                    acc += 0.8f * ((t != 0.0f) ? a : bb);
                }
            }
            if (intile) s_mask[(row - 1) * TW + lane] = (unsigned char)mask;
        }
    }
    // epilogue: halo cols 0 and 33 (8c * 18row * 2 = 288 elements)
    for (int idx = tid; idx < C_ * HH_ * 2; idx += NTHREADS) {
        int c   = idx / (HH_ * 2);
        int rem = idx - c * (HH_ * 2);
        int row = rem >> 1;
        int wx  = (rem & 1) ? 33 : 0;
        int gh  = h0 - 1 + row;
        int gw  = w0 - 1 + wx;
        float p = 0.0f, lp = -1e9f;
        if (((unsigned)gh < H_) && ((unsigned)gw < W_)) {
            float x = cmap[((long)(b * C_ + c) * H_ + gh) * W_ + gw];
            sigmoid_pair(x, p, lp);
        }
        int si = (c * HH_ + row) * SROW + wx;
        s_p[si]  = p;
        s_lp[si] = lp;
    }
    __syncthreads();

    // ==== compute phase: 1 px/lane, 2 rows/thread; conflict-free LDS only.
    // vote k: center ch k  x  ch 7-k at neighbor offset (DH[k], DW[k])
    const int DH[8] = {-1, -1, -1,  0, 0,  1, 1, 1};
    const int DW[8] = {-1,  0,  1, -1, 1, -1, 0, 1};

    #pragma unroll
    for (int q = 0; q < 2; q++) {
        const int py = wrp + q * 8;          // tile row 0..15
        const int gh = h0 + py;
        const int gw = w0 + lane;
        const int sbase = (py + 1) * SROW + lane + 1;
        const unsigned mask = s_mask[py * TW + lane];

        float pc[8], lpc[8];
        #pragma unroll
        for (int c = 0; c < 8; c++) {
            int si = c * (HH_ * SROW) + sbase;
            pc[c]  = s_p[si];
            lpc[c] = s_lp[si];
        }

        // votes / bimap BCE (w=0.2)
        float vmin = 1e30f, vsum = 0.0f;
        #pragma unroll
        for (int k = 0; k < 8; k++) {
            int ni = (7 - k) * (HH_ * SROW) + (py + 1 + DH[k]) * SROW
                     + (lane + 1 + DW[k]);
            float np  = s_p[ni];
            float nlp = s_lp[ni];
            float v    = pc[k] * np;
            float lv   = fmaxf(lpc[k] + nlp, -100.0f);       // log(pa*pb), free
            float l1mv = fmaxf(__logf(fmaf(-pc[k], np, 1.0f)), -100.0f);
            acc += 0.2f * (((mask >> k) & 1u) ? lv : l1mv);
            vmin = fminf(vmin, v);
            vsum += v;
        }

        // decouple / de loss (w=1.0): one logf via argument select
        bool  edge = (mask != 0u) && (mask != 0xFFu);
        float glo  = vsum * 0.125f;
        float da   = edge ? (1.0f - vmin) : glo;            // decouple_map
        float db   = edge ? vmin : (1.0f - glo);            // 1 - decouple_map
        float tt   = __ldcs(&target[((size_t)b * H_ + gh) * W_ + gw]);
        float arg  = (tt != 0.0f) ? da : db;
        acc += fmaxf(__logf(arg), -100.0f);
    }

    // ==== block reduction + global accumulate ==============================
    #pragma unroll
    for (int off = 16; off; off >>= 1)
        acc += __shfl_xor_sync(0xFFFFFFFFu, acc, off);

    __shared__ float warpsum[8];
    if (lane == 0) warpsum[wrp] = acc;
    __syncthreads();
    if (tid < 8) {
        float v = warpsum[tid];
        #pragma unroll
        for (int off = 4; off; off >>= 1)
            v += __shfl_xor_sync(0xFFu, v, off);
        if (tid == 0) atomicAdd(&g_acc, (double)v);
    }

    // ==== last block finalizes: write out, reset for next graph replay =====
    if (tid == 0) {
        __threadfence();
        unsigned t = atomicAdd(&g_tick, 1u);
        if (t == (unsigned)(NBLOCKS - 1)) {
            __threadfence();
            double total = atomicAdd(&g_acc, 0.0);
            out[0] = (float)(-total);
            g_acc  = 0.0;
            g_tick = 0u;
            __threadfence();
        }
    }
}

extern "C" void kernel_launch(void* const* d_in, const int* in_sizes, int n_in,
                              void* d_out, int out_size) {
    const float* cmap   = (const float*)d_in[0];
    const float* target = (const float*)d_in[1];
    const float* con    = (const float*)d_in[2];

    dim3 grid(W_ / TW, H_ / TH, B_);
    k_main<<<grid, NTHREADS>>>(cmap, target, con, (float*)d_out);
}